// round 12
// baseline (speedup 1.0000x reference)
#include <cuda_runtime.h>
#include <cuda_fp16.h>
#include <math.h>

#define NN 100000
#define NE 1600000
#define IND 128
#define HID 64

// ---------------- scratch (device globals; never host-passed) ---------------
__device__ __half d_xw_h[(size_t)NN * HID]; // dinv-prescaled X@W rows, fp16
__device__ float  d_agg[(size_t)NN * HID];  // h buffer (fp32)
__device__ float  d_dinv[NN];
__device__ int    d_deg[NN];
__device__ int    d_off[NN + 1];
__device__ int    d_cursor[NN];
__device__ int    d_csrc[NE];
__device__ float  d_g[HID];
__device__ int    d_idx64;

// PLANAR layout: src = ei[0..E), dst = ei[E..2E)
__device__ __forceinline__ int edge_src(const void* ei, size_t e, int is64) {
    long long v = is64 ? ((const long long*)ei)[e] : (long long)((const int*)ei)[e];
    return (int)((unsigned long long)v % NN);
}
__device__ __forceinline__ int edge_dst(const void* ei, size_t e, int is64) {
    long long v = is64 ? ((const long long*)ei)[(size_t)NE + e]
                       : (long long)((const int*)ei)[(size_t)NE + e];
    return (int)((unsigned long long)v % NN);
}

// ---------------- init + dtype detect (merged) ------------------------------
__global__ void k_initdetect(const int* __restrict__ ei) {
    int i = blockIdx.x * blockDim.x + threadIdx.x;
    if (i < NN) d_deg[i] = 0;
    if (i < HID) d_g[i] = 0.0f;
    if (blockIdx.x == 0) {
        __shared__ int found;
        if (threadIdx.x == 0) found = 0;
        __syncthreads();
        for (int k = threadIdx.x; k < 4096; k += blockDim.x)
            if (ei[2 * k + 1] != 0) found = 1;       // benign race
        __syncthreads();
        if (threadIdx.x == 0) d_idx64 = found ? 0 : 1;
    }
}

// ---------------- degree count ----------------------------------------------
__global__ void k_deg(const void* __restrict__ ei) {
    int e = blockIdx.x * blockDim.x + threadIdx.x;
    int is64 = d_idx64;
    if (e < NE) atomicAdd(&d_deg[edge_dst(ei, e, is64)], 1);
}

// ---------------- scan + dinv (merged, single block) -------------------------
__global__ void k_scandinv() {
    __shared__ int part[1024];
    int t = threadIdx.x;
    for (int i = t; i < NN; i += 1024)
        d_dinv[i] = rsqrtf((float)d_deg[i] + 1.0f);
    const int CH = (NN + 1023) / 1024;
    int beg = t * CH, end = min(beg + CH, NN);
    int s = 0;
    for (int i = beg; i < end; i++) s += d_deg[i];
    part[t] = s;
    __syncthreads();
    for (int off = 1; off < 1024; off <<= 1) {
        int v = (t >= off) ? part[t - off] : 0;
        __syncthreads();
        part[t] += v;
        __syncthreads();
    }
    int run = (t == 0) ? 0 : part[t - 1];
    for (int i = beg; i < end; i++) {
        d_off[i] = run;
        d_cursor[i] = run;
        run += d_deg[i];
    }
    if (t == 1023) d_off[NN] = run;
}

// ---------------- CSR fill ----------------------------------------------------
__global__ void k_fill(const void* __restrict__ ei) {
    int e = blockIdx.x * blockDim.x + threadIdx.x;
    if (e >= NE) return;
    int is64 = d_idx64;
    int s = edge_src(ei, e, is64);
    int d = edge_dst(ei, e, is64);
    int pos = atomicAdd(&d_cursor[d], 1);
    d_csrc[pos] = s;
}

// ---------------- register-tiled GEMM: d_xw_h = fp16( dinv .* (X @ W) ) -----
// 128 threads/block; tile = 128 nodes x 64 cols; thread = 8 nodes x 8 cols.
// Xs stored TRANSPOSED [k][node] so xv loads are 2x LDS.128.
template <int K, int LAYER>
__global__ void k_gemm(const float* __restrict__ Xext, const float* __restrict__ W) {
    __shared__ float Ws[K * HID];       // full W resident
    __shared__ float Xs[32][132];       // [k-slice][128 nodes + pad]
    const float* X = (LAYER == 1) ? Xext : d_agg;
    int tid = threadIdx.x;
    int ty = tid >> 3, tx = tid & 7;
    int base = blockIdx.x * 128;

    for (int i = tid; i < K * HID / 4; i += 128)
        reinterpret_cast<float4*>(Ws)[i] = reinterpret_cast<const float4*>(W)[i];

    float acc[8][8];
#pragma unroll
    for (int m = 0; m < 8; m++)
#pragma unroll
        for (int n = 0; n < 8; n++) acc[m][n] = 0.0f;

    for (int kc = 0; kc < K; kc += 32) {
        __syncthreads();
        // coalesced load, transposed store: 128 rows x 8 float4
#pragma unroll
        for (int p = 0; p < 8; p++) {
            int i = p * 128 + tid;
            int r = i >> 3;               // node row 0..127
            int c4 = i & 7;               // k-quad 0..7
            float4 v = make_float4(0.f, 0.f, 0.f, 0.f);
            if (base + r < NN)
                v = *reinterpret_cast<const float4*>(
                        &X[(size_t)(base + r) * K + kc + c4 * 4]);
            Xs[c4 * 4 + 0][r] = v.x;
            Xs[c4 * 4 + 1][r] = v.y;
            Xs[c4 * 4 + 2][r] = v.z;
            Xs[c4 * 4 + 3][r] = v.w;
        }
        __syncthreads();
#pragma unroll
        for (int c = 0; c < 32; c++) {
            float xv[8], wv[8];
            const float4* xr = reinterpret_cast<const float4*>(&Xs[c][ty * 8]);
            float4 x0 = xr[0], x1 = xr[1];
            xv[0] = x0.x; xv[1] = x0.y; xv[2] = x0.z; xv[3] = x0.w;
            xv[4] = x1.x; xv[5] = x1.y; xv[6] = x1.z; xv[7] = x1.w;
            const float4* wr = reinterpret_cast<const float4*>(&Ws[(kc + c) * HID + tx * 8]);
            float4 w0 = wr[0], w1 = wr[1];
            wv[0] = w0.x; wv[1] = w0.y; wv[2] = w0.z; wv[3] = w0.w;
            wv[4] = w1.x; wv[5] = w1.y; wv[6] = w1.z; wv[7] = w1.w;
#pragma unroll
            for (int m = 0; m < 8; m++)
#pragma unroll
                for (int n = 0; n < 8; n++) acc[m][n] += xv[m] * wv[n];
        }
    }

    // epilogue: per node, scale by dinv, fp16, 16B store
#pragma unroll
    for (int m = 0; m < 8; m++) {
        int node = base + ty * 8 + m;
        if (node >= NN) break;
        float sc = d_dinv[node];
        __half2 h[4];
#pragma unroll
        for (int n = 0; n < 4; n++)
            h[n] = __floats2half2_rn(acc[m][2 * n] * sc, acc[m][2 * n + 1] * sc);
        *reinterpret_cast<float4*>(d_xw_h + (size_t)node * HID + tx * 8) =
            *reinterpret_cast<const float4*>(h);
    }
}

// ---------------- gather: 8 lanes/node; half2 accumulation -------------------
__device__ __forceinline__ void hacc(uint4 v, __half2* a) {
    a[0] = __hadd2(a[0], *reinterpret_cast<const __half2*>(&v.x));
    a[1] = __hadd2(a[1], *reinterpret_cast<const __half2*>(&v.y));
    a[2] = __hadd2(a[2], *reinterpret_cast<const __half2*>(&v.z));
    a[3] = __hadd2(a[3], *reinterpret_cast<const __half2*>(&v.w));
}

__global__ void k_gather(const float* __restrict__ bias) {
    int node = blockIdx.x * (blockDim.x >> 3) + (threadIdx.x >> 3);
    int lane = threadIdx.x & 7;
    if (node >= NN) return;

    const uint4* base = reinterpret_cast<const uint4*>(d_xw_h) + lane;  // +node*8
    __half2 a[4];
    {   // self-loop (row already dinv-scaled)
        uint4 sv = base[(size_t)node * 8];
        a[0] = *reinterpret_cast<const __half2*>(&sv.x);
        a[1] = *reinterpret_cast<const __half2*>(&sv.y);
        a[2] = *reinterpret_cast<const __half2*>(&sv.z);
        a[3] = *reinterpret_cast<const __half2*>(&sv.w);
    }

    int beg = d_off[node], end = d_off[node + 1];
    int k = beg;
    for (; k + 4 <= end; k += 4) {
        int s0 = d_csrc[k], s1 = d_csrc[k + 1], s2 = d_csrc[k + 2], s3 = d_csrc[k + 3];
        uint4 v0 = base[(size_t)s0 * 8];
        uint4 v1 = base[(size_t)s1 * 8];
        uint4 v2 = base[(size_t)s2 * 8];
        uint4 v3 = base[(size_t)s3 * 8];
        hacc(v0, a); hacc(v1, a); hacc(v2, a); hacc(v3, a);
    }
    for (; k < end; k++) {
        uint4 v = base[(size_t)d_csrc[k] * 8];
        hacc(v, a);
    }

    float dd = d_dinv[node];
    const float* b = bias + lane * 8;
    float r[8];
#pragma unroll
    for (int i = 0; i < 4; i++) {
        float2 f = __half22float2(a[i]);
        r[2 * i]     = fmaxf(f.x * dd + b[2 * i], 0.0f);
        r[2 * i + 1] = fmaxf(f.y * dd + b[2 * i + 1], 0.0f);
    }

    float4* out = reinterpret_cast<float4*>(&d_agg[(size_t)node * HID + lane * 8]);
    out[0] = make_float4(r[0], r[1], r[2], r[3]);
    out[1] = make_float4(r[4], r[5], r[6], r[7]);
}

// ---------------- column reduce of d_agg into d_g ---------------------------
__global__ void k_reduce() {
    __shared__ float sh[256];
    int tid = threadIdx.x;
    size_t stride = (size_t)gridDim.x * blockDim.x;
    float bsum = 0.0f;
    for (size_t i = (size_t)blockIdx.x * blockDim.x + tid; i < (size_t)NN * HID; i += stride)
        bsum += d_agg[i];
    sh[tid] = bsum;
    __syncthreads();
    if (tid < HID) {
        float tot = sh[tid] + sh[tid + 64] + sh[tid + 128] + sh[tid + 192];
        atomicAdd(&d_g[tid], tot);
    }
}

// ---------------- final: sigmoid(mean(h2) @ Wf + bf) ------------------------
__global__ void k_final(const float* __restrict__ Wf, const float* __restrict__ bf,
                        float* __restrict__ out) {
    __shared__ float sh[HID];
    int j = threadIdx.x;
    sh[j] = d_g[j] * (1.0f / (float)NN) * Wf[j];
    __syncthreads();
    if (j < 32) sh[j] += sh[j + 32];
    __syncthreads();
    if (j == 0) {
        float s = 0.0f;
#pragma unroll
        for (int i = 0; i < 32; i++) s += sh[i];
        out[0] = 1.0f / (1.0f + expf(-(s + bf[0])));
    }
}

extern "C" void kernel_launch(void* const* d_in, const int* in_sizes, int n_in,
                              void* d_out, int out_size) {
    const float* x   = (const float*)d_in[0];
    const void*  ei  = d_in[1];
    const float* W1  = (const float*)d_in[2];
    const float* b1  = (const float*)d_in[3];
    const float* W2  = (const float*)d_in[4];
    const float* b2  = (const float*)d_in[5];
    const float* Wf  = (const float*)d_in[6];
    const float* bf  = (const float*)d_in[7];
    float* out = (float*)d_out;

    const int T = 256;
    int nblk_n = (NN + T - 1) / T;
    int nblk_e = (NE + T - 1) / T;
    int nblk_g = (NN * 8 + T - 1) / T;

    k_initdetect<<<nblk_n, T>>>((const int*)ei);        // 1
    k_deg<<<nblk_e, T>>>(ei);                           // 2
    k_scandinv<<<1, 1024>>>();                          // 3
    k_fill<<<nblk_e, T>>>(ei);                          // 4
    k_gemm<IND, 1><<<(NN + 127) / 128, 128>>>(x, W1);   // 5
    k_gather<<<nblk_g, T>>>(b1);                        // 6
    k_gemm<HID, 2><<<(NN + 127) / 128, 128>>>(nullptr, W2);  // 7
    k_gather<<<nblk_g, T>>>(b2);                             // 8
    k_reduce<<<1024, T>>>();                            // 9
    k_final<<<1, HID>>>(Wf, bf, out);                   // 10
}